// round 16
// baseline (speedup 1.0000x reference)
#include <cuda_runtime.h>
#include <cuda_bf16.h>
#include <math.h>

#define BSZ 4096
#define HD  128
#define TDIM 768

// ---------------- device scratch ----------------
__device__ __align__(16) float g_LN[BSZ * HD];   // normalized logits fp32
__device__ __align__(16) char g_LN8[BSZ * HD];   // normalized logits int8 (x127)
__device__ float g_Tn[BSZ];                       // teacher row inv-norms
__device__ __align__(16) char g_Ht8[HD * BSZ];    // hash^T int8 (+-1) [128][4096]
__device__ __align__(16) char g_Tt8[TDIM * BSZ];  // norm teacher^T int8 (x400)
__device__ float g_GH[HD * HD];
__device__ float g_C [HD * TDIM];
__device__ float g_TT[TDIM * TDIM];
__device__ unsigned g_bm[BSZ * BSZ / 32];  // mask bits [4096][128] u32
__device__ float g_denom[BSZ];
__device__ float g_pos[BSZ];
__device__ float g_cnt[BSZ];
__device__ float g_qrow[BSZ];              // per-row quant sums
__device__ float g_ST;

__device__ __forceinline__ void mma_s8(int* d, const unsigned* a, const unsigned* b) {
    asm volatile(
        "mma.sync.aligned.m16n8k32.row.col.s32.s8.s8.s32 "
        "{%0,%1,%2,%3}, {%4,%5,%6,%7}, {%8,%9}, {%0,%1,%2,%3};"
        : "+r"(d[0]), "+r"(d[1]), "+r"(d[2]), "+r"(d[3])
        : "r"(a[0]), "r"(a[1]), "r"(a[2]), "r"(a[3]), "r"(b[0]), "r"(b[1]));
}

#define LDSM4(r0, r1, r2, r3, addr)                                         \
    asm volatile("ldmatrix.sync.aligned.m8n8.x4.shared.b16 {%0,%1,%2,%3}, [%4];" \
        : "=r"(r0), "=r"(r1), "=r"(r2), "=r"(r3) : "r"(addr))

// ---------------- mask -> bitmask (coalesced ballot) ----------------
__global__ void k_bits(const int* __restrict__ pmask) {
    int gi = blockIdx.x * 256 + threadIdx.x;
    int warp = gi >> 5;                  // 16384 warps
    int lane = threadIdx.x & 31;
    long base = (long)warp * 1024;
    unsigned myword = 0;
    #pragma unroll
    for (int s = 0; s < 32; s++) {
        int v = pmask[base + s * 32 + lane];
        unsigned b = __ballot_sync(0xffffffffu, v != 0);
        if (lane == s) myword = b;
    }
    g_bm[base / 32 + lane] = myword;
}

// ---------------- normalize logits + per-row quant + denom zero -------------
__global__ void k_norm_logits(const float* __restrict__ x) {
    int row = blockIdx.x;
    int t = threadIdx.x;                 // 128 threads
    float v = x[row * HD + t];
    float ss = v * v;
    float q = fabsf(fabsf(v) - 1.0f);
    #pragma unroll
    for (int o = 16; o >= 1; o >>= 1) {
        ss += __shfl_xor_sync(0xffffffffu, ss, o);
        q  += __shfl_xor_sync(0xffffffffu, q, o);
    }
    __shared__ float sred[4], qred[4];
    __shared__ float sinv;
    int w = t >> 5, l = t & 31;
    if (l == 0) { sred[w] = ss; qred[w] = q; }
    __syncthreads();
    if (t == 0) {
        float tot = sred[0] + sred[1] + sred[2] + sred[3];
        g_qrow[row] = qred[0] + qred[1] + qred[2] + qred[3];
        g_denom[row] = 0.f;
        sinv = 1.0f / fmaxf(sqrtf(tot), 1e-12f);
    }
    __syncthreads();
    float nv = v * sinv;
    g_LN[row * HD + t] = nv;
    g_LN8[row * HD + t] = (char)__float2int_rn(nv * 127.0f);
}

// ---------------- positives: warp-per-row bitmask scan, exact fp32 ----------
__global__ void k_posbits() {
    int warp = (blockIdx.x * blockDim.x + threadIdx.x) >> 5;   // 4096 warps
    int lane = threadIdx.x & 31;
    int row = warp;
    const float4* LN4 = (const float4*)g_LN;   // row stride 32 float4
    float4 a = LN4[row * 32 + lane];
    float ps = 0.f;
    int cnt = 0;
    #pragma unroll
    for (int g = 0; g < 4; g++) {
        unsigned wrd = g_bm[row * 128 + g * 32 + lane];
        unsigned act = __ballot_sync(0xffffffffu, wrd != 0);
        while (act) {
            int src = __ffs(act) - 1; act &= act - 1;
            unsigned w2 = __shfl_sync(0xffffffffu, wrd, src);
            int base = (g * 32 + src) * 32;
            while (w2) {
                int b = __ffs(w2) - 1; w2 &= w2 - 1;
                int j = base + b;
                float4 bb = LN4[j * 32 + lane];
                float d = a.x * bb.x + a.y * bb.y + a.z * bb.z + a.w * bb.w;
                #pragma unroll
                for (int o = 16; o >= 1; o >>= 1)
                    d += __shfl_xor_sync(0xffffffffu, d, o);
                ps += d; cnt++;
            }
        }
    }
    if (lane == 0) { g_pos[row] = ps * 5.0f; g_cnt[row] = (float)cnt; }
}

// ---------------- teacher row inv norms + Gram-accumulator zeroing ----------
__global__ void k_tnorm(const float* __restrict__ x) {
    int gi = blockIdx.x * 256 + threadIdx.x;
    int n = gridDim.x * 256;
    for (int j = gi; j < TDIM * TDIM; j += n) g_TT[j] = 0.f;
    for (int j = gi; j < HD * TDIM;  j += n) g_C[j]  = 0.f;
    if (gi < HD * HD) g_GH[gi] = 0.f;
    if (gi == 0) g_ST = 0.f;
    int row = gi >> 5;                   // 4096 warps
    int lane = threadIdx.x & 31;
    const float4* x4 = (const float4*)(x + row * TDIM);  // 192 float4
    float ss = 0.f;
    #pragma unroll
    for (int i = 0; i < 6; i++) {
        float4 v = x4[lane + i * 32];
        ss += v.x * v.x + v.y * v.y + v.z * v.z + v.w * v.w;
    }
    #pragma unroll
    for (int o = 16; o >= 1; o >>= 1) ss += __shfl_xor_sync(0xffffffffu, ss, o);
    if (lane == 0) g_Tn[row] = 1.0f / fmaxf(sqrtf(ss), 1e-12f);
}

// ---------------- fused transposes -> int8 (hash +-1, teacher x400) ---------
__global__ void k_transpose_both(const float* __restrict__ hash,
                                 const float* __restrict__ teach) {
    __shared__ float t[32][33];
    int x = threadIdx.x, y = threadIdx.y;   // block (32, 8)
    int r0 = blockIdx.y * 32;
    if (blockIdx.x < 4) {
        int c0 = blockIdx.x * 32;
        #pragma unroll
        for (int i = 0; i < 32; i += 8) t[y + i][x] = hash[(r0 + y + i) * HD + c0 + x];
        __syncthreads();
        #pragma unroll
        for (int i = 0; i < 32; i += 8)
            g_Ht8[(c0 + y + i) * BSZ + r0 + x] = (char)__float2int_rn(t[x][y + i]);
    } else {
        int c0 = (blockIdx.x - 4) * 32;
        #pragma unroll
        for (int i = 0; i < 32; i += 8)
            t[y + i][x] = teach[(r0 + y + i) * TDIM + c0 + x] * g_Tn[r0 + y + i];
        __syncthreads();
        #pragma unroll
        for (int i = 0; i < 32; i += 8) {
            float v = fminf(fmaxf(t[x][y + i] * 400.0f, -127.0f), 127.0f);
            g_Tt8[(c0 + y + i) * BSZ + r0 + x] = (char)__float2int_rn(v);
        }
    }
}

// ======== int8 m16n8k32 mma cores (LDSM b16 trick: 1 b16 = 2 int8) ========

#define LDG8(Aexpr, Bexpr)                                                  \
    do {                                                                    \
        _Pragma("unroll")                                                   \
        for (int s = 0; s < 2; s++) {                                       \
            int idx = tid + s * 256;                                        \
            int r = idx >> 2, c4 = idx & 3;                                 \
            ga[s] = (Aexpr); gb[s] = (Bexpr);                               \
        }                                                                   \
    } while (0)

#define STS8(st)                                                            \
    do {                                                                    \
        _Pragma("unroll")                                                   \
        for (int s = 0; s < 2; s++) {                                       \
            int idx = tid + s * 256;                                        \
            int r = idx >> 2, c4 = idx & 3;                                 \
            *(uint4*)&As8[st][r][c4 * 4] = ga[s];                           \
            *(uint4*)&Bs8[st][r][c4 * 4] = gb[s];                           \
        }                                                                   \
    } while (0)

// stride-20 bases (gemm_all, chunk k=64 int8 = 16 u32 used)
#define LDSM_BASES20()                                                      \
    unsigned aBase = (unsigned)__cvta_generic_to_shared(&As8[0][0][0])      \
        + (((wm * 64 + (lane & 7) + ((lane >> 3) & 1) * 8) * 20             \
            + (lane >> 4) * 4) << 2);                                       \
    unsigned bBase = (unsigned)__cvta_generic_to_shared(&Bs8[0][0][0])      \
        + (((wn * 32 + (lane & 7) + (lane >> 4) * 8) * 20                   \
            + ((lane >> 3) & 1) * 4) << 2)

#define MMA8_CHUNK20(st)                                                    \
    do {                                                                    \
        _Pragma("unroll")                                                   \
        for (int kk = 0; kk < 2; kk++) {                                    \
            int kb = kk * 8;                                                \
            unsigned af[4][4], bf[4][2];                                    \
            _Pragma("unroll")                                               \
            for (int mi = 0; mi < 4; mi++)                                  \
                LDSM4(af[mi][0], af[mi][1], af[mi][2], af[mi][3],           \
                      aBase + (st) * 10240 + ((mi * 16 * 20 + kb) << 2));   \
            _Pragma("unroll")                                               \
            for (int n2 = 0; n2 < 2; n2++)                                  \
                LDSM4(bf[2 * n2][0], bf[2 * n2][1],                         \
                      bf[2 * n2 + 1][0], bf[2 * n2 + 1][1],                 \
                      bBase + (st) * 10240 + ((n2 * 16 * 20 + kb) << 2));   \
            _Pragma("unroll")                                               \
            for (int mi = 0; mi < 4; mi++)                                  \
                _Pragma("unroll")                                           \
                for (int ni = 0; ni < 4; ni++)                              \
                    mma_s8(acc[mi][ni], af[mi], bf[ni]);                    \
        }                                                                   \
    } while (0)

// ---------------- ALL Gram GEMMs in one launch (int8, task-decoded) --------
// blocks 0..167: TT (21 tiles x 8 splits, kPer=512); 168..215: C (6x8);
// 216..223: GH (8 splits). Chunk = 64 int8.
__global__ void __launch_bounds__(256) k_gemm_all() {
    __shared__ __align__(16) unsigned As8[2][128][20];
    __shared__ __align__(16) unsigned Bs8[2][128][20];
    int id = blockIdx.x;
    const char *Ap, *Bp;
    float* out;
    float scale;
    int ldo, m0, n0, kBeg;
    if (id < 168) {
        int tile = id >> 3, split = id & 7;
        int tm = 0, t = tile;
        while (t >= 6 - tm) { t -= 6 - tm; tm++; }
        m0 = tm * 128; n0 = (tm + t) * 128;
        kBeg = split * 512;
        Ap = g_Tt8; Bp = g_Tt8; out = g_TT; ldo = TDIM; scale = 1.f / 160000.f;
    } else if (id < 216) {
        int t = id - 168;
        int tile = t >> 3, split = t & 7;
        m0 = 0; n0 = tile * 128;
        kBeg = split * 512;
        Ap = g_Ht8; Bp = g_Tt8; out = g_C; ldo = TDIM; scale = 1.f / 400.f;
    } else {
        int split = id - 216;
        m0 = 0; n0 = 0;
        kBeg = split * 512;
        Ap = g_Ht8; Bp = g_Ht8; out = g_GH; ldo = HD; scale = 1.f;
    }
    int tid = threadIdx.x, lane = tid & 31, w = tid >> 5;
    int wm = w & 1, wn = w >> 1;
    int fr = lane >> 2, fc = lane & 3;
    LDSM_BASES20();
    const uint4* A4 = (const uint4*)Ap;    // row = 256 uint4 (4096 int8)
    const uint4* B4 = (const uint4*)Bp;
    int acc[4][4][4] = {};
    uint4 ga[2], gb[2];
    LDG8(A4[(m0 + r) * 256 + (kBeg >> 4) + c4],
         B4[(n0 + r) * 256 + (kBeg >> 4) + c4]);
    STS8(0);
    __syncthreads();
    for (int c = 0; c < 8; c++) {
        int st = c & 1;
        if (c + 1 < 8) {
            int kc = kBeg + (c + 1) * 64;
            LDG8(A4[(m0 + r) * 256 + (kc >> 4) + c4],
                 B4[(n0 + r) * 256 + (kc >> 4) + c4]);
        }
        MMA8_CHUNK20(st);
        if (c + 1 < 8) STS8(1 - st);
        __syncthreads();
    }
    #pragma unroll
    for (int mi = 0; mi < 4; mi++)
        #pragma unroll
        for (int ni = 0; ni < 4; ni++)
            #pragma unroll
            for (int h = 0; h < 2; h++)
                #pragma unroll
                for (int q = 0; q < 2; q++) {
                    int gi = m0 + wm * 64 + mi * 16 + fr + h * 8;
                    int gj = n0 + wn * 32 + ni * 8 + fc * 2 + q;
                    atomicAdd(&out[gi * ldo + gj],
                              scale * (float)acc[mi][ni][h * 2 + q]);
                }
}

// ---------------- distill square-reduce ----------------
__global__ void k_sq3() {
    int i = blockIdx.x * 256 + threadIdx.x;
    int n = gridDim.x * 256;
    float s = 0.f;
    for (int j = i; j < HD * HD; j += n) {
        float v = g_GH[j]; s += v * v * (1.f / (128.f * 128.f));
    }
    for (int j = i; j < HD * TDIM; j += n) {
        float v = g_C[j]; s -= 2.f * v * v * (1.f / 128.f);
    }
    for (int j = i; j < TDIM * TDIM; j += n) {
        int r = j / TDIM, c = j % TDIM;
        if (c < r) continue;
        float v = g_TT[j];
        s += (c == r) ? v * v : 2.f * v * v;
    }
    #pragma unroll
    for (int o = 16; o >= 1; o >>= 1) s += __shfl_xor_sync(0xffffffffu, s, o);
    __shared__ float red[8];
    if ((threadIdx.x & 31) == 0) red[threadIdx.x >> 5] = s;
    __syncthreads();
    if (threadIdx.x == 0) {
        float tot = 0.f;
        #pragma unroll
        for (int k = 0; k < 8; k++) tot += red[k];
        atomicAdd(&g_ST, tot / ((float)BSZ * (float)BSZ));
    }
}

// ---------------- contrastive: full-K int8 tiles, denominator only ----------
// static smem: As [128][36] u32 + Bs [128][36] u32 = 36,864 B; one sync.
__global__ void __launch_bounds__(256) k_cont() {
    __shared__ __align__(16) unsigned As8[128][36];
    __shared__ __align__(16) unsigned Bs8[128][36];
    __shared__ float sCd[128];
    int t = blockIdx.x, tm = 0;                 // 32x32 tiles, upper = 528
    while (t >= 32 - tm) { t -= 32 - tm; tm++; }
    int i0 = tm * 128, j0 = (tm + t) * 128;
    bool diag = (i0 == j0);
    int tid = threadIdx.x, lane = tid & 31, w = tid >> 5;
    int wm = w & 1, wn = w >> 1;
    int fr = lane >> 2, fc = lane & 3;
    unsigned aBase = (unsigned)__cvta_generic_to_shared(&As8[0][0])
        + (((wm * 64 + (lane & 7) + ((lane >> 3) & 1) * 8) * 36
            + (lane >> 4) * 4) << 2);
    unsigned bBase = (unsigned)__cvta_generic_to_shared(&Bs8[0][0])
        + (((wn * 32 + (lane & 7) + (lane >> 4) * 8) * 36
            + ((lane >> 3) & 1) * 4) << 2);
    if (tid < 128) sCd[tid] = 0.f;
    const uint4* LN4 = (const uint4*)g_LN8;   // row = 8 uint4 (128 int8)
    #pragma unroll
    for (int s = 0; s < 4; s++) {
        int idx = tid + s * 256;
        int r = idx >> 3, c4 = idx & 7;
        *(uint4*)&As8[r][c4 * 4] = LN4[(i0 + r) * 8 + c4];
        *(uint4*)&Bs8[r][c4 * 4] = LN4[(j0 + r) * 8 + c4];
    }
    __syncthreads();
    int acc[4][4][4] = {};
    #pragma unroll
    for (int kk = 0; kk < 4; kk++) {
        int kb = kk * 8;
        unsigned af[4][4], bf[4][2];
        #pragma unroll
        for (int mi = 0; mi < 4; mi++)
            LDSM4(af[mi][0], af[mi][1], af[mi][2], af[mi][3],
                  aBase + ((mi * 16 * 36 + kb) << 2));
        #pragma unroll
        for (int n2 = 0; n2 < 2; n2++)
            LDSM4(bf[2 * n2][0], bf[2 * n2][1],
                  bf[2 * n2 + 1][0], bf[2 * n2 + 1][1],
                  bBase + ((n2 * 16 * 36 + kb) << 2));
        #pragma unroll
        for (int mi = 0; mi < 4; mi++)
            #pragma unroll
            for (int ni = 0; ni < 4; ni++)
                mma_s8(acc[mi][ni], af[mi], bf[ni]);
    }

    // ---- epilogue: exp sums, both orientations ----
    const float SCL = 5.0f / 16129.0f;   // 5 / 127^2
    float dR[4][2] = {}, dC[4][2] = {};
    #pragma unroll
    for (int mi = 0; mi < 4; mi++)
        #pragma unroll
        for (int ni = 0; ni < 4; ni++)
            #pragma unroll
            for (int h = 0; h < 2; h++)
                #pragma unroll
                for (int q = 0; q < 2; q++) {
                    int li = wm * 64 + mi * 16 + fr + h * 8;
                    int lj = wn * 32 + ni * 8 + fc * 2 + q;
                    float e = __expf((float)acc[mi][ni][h * 2 + q] * SCL);
                    if (!diag || li != lj) dR[mi][h] += e;
                    if (!diag) dC[ni][q] += e;
                }
    #pragma unroll
    for (int mi = 0; mi < 4; mi++)
        #pragma unroll
        for (int h = 0; h < 2; h++) {
            #pragma unroll
            for (int o = 2; o >= 1; o >>= 1)
                dR[mi][h] += __shfl_down_sync(0xffffffffu, dR[mi][h], o, 4);
            if (fc == 0)
                atomicAdd(&g_denom[i0 + wm * 64 + mi * 16 + fr + h * 8], dR[mi][h]);
        }
    if (!diag) {
        #pragma unroll
        for (int ni = 0; ni < 4; ni++)
            #pragma unroll
            for (int q = 0; q < 2; q++) {
                #pragma unroll
                for (int o = 16; o >= 4; o >>= 1)
                    dC[ni][q] += __shfl_xor_sync(0xffffffffu, dC[ni][q], o);
                if (fr == 0)
                    atomicAdd(&sCd[wn * 32 + ni * 8 + fc * 2 + q], dC[ni][q]);
            }
        __syncthreads();
        if (tid < 128) atomicAdd(&g_denom[j0 + tid], sCd[tid]);
    }
}

// ---------------- final combine ----------------
__global__ void k_combine(float* __restrict__ out) {
    int tid = threadIdx.x;               // 256 threads
    float cont = 0.f, qs = 0.f;
    for (int i = tid; i < BSZ; i += 256) {
        cont += logf(g_denom[i]) - g_pos[i] / fmaxf(g_cnt[i], 1.0f);
        qs   += g_qrow[i];
    }
    #pragma unroll
    for (int o = 16; o >= 1; o >>= 1) {
        cont += __shfl_xor_sync(0xffffffffu, cont, o);
        qs   += __shfl_xor_sync(0xffffffffu, qs, o);
    }
    __shared__ float r0[8], r1[8];
    if ((tid & 31) == 0) { r0[tid >> 5] = cont; r1[tid >> 5] = qs; }
    __syncthreads();
    if (tid == 0) {
        float cT = 0.f, qT = 0.f;
        #pragma unroll
        for (int i = 0; i < 8; i++) { cT += r0[i]; qT += r1[i]; }
        float quant = qT / ((float)BSZ * (float)HD);
        out[0] = cT / (float)BSZ + 0.5f * g_ST + 0.01f * quant;
    }
}

// ---------------- launch: fork-join across 3 streams ----------------
extern "C" void kernel_launch(void* const* d_in, const int* in_sizes, int n_in,
                              void* d_out, int out_size) {
    const float* logits = (const float*)d_in[0];
    const float* hash   = (const float*)d_in[1];
    const float* teach  = (const float*)d_in[2];
    const int*   pmask  = (const int*)d_in[3];
    float* out = (float*)d_out;

    static cudaStream_t s1 = 0, s2 = 0;
    static cudaEvent_t evStart = 0, evA = 0, ev1 = 0, ev2 = 0;
    if (s1 == 0) {
        cudaStreamCreateWithFlags(&s1, cudaStreamNonBlocking);
        cudaStreamCreateWithFlags(&s2, cudaStreamNonBlocking);
        cudaEventCreateWithFlags(&evStart, cudaEventDisableTiming);
        cudaEventCreateWithFlags(&evA, cudaEventDisableTiming);
        cudaEventCreateWithFlags(&ev1, cudaEventDisableTiming);
        cudaEventCreateWithFlags(&ev2, cudaEventDisableTiming);
    }
    cudaStream_t s0 = 0;   // legacy default (capture) stream

    cudaEventRecord(evStart, s0);
    cudaStreamWaitEvent(s1, evStart, 0);
    cudaStreamWaitEvent(s2, evStart, 0);

    // ---- main: logits chain (+denom zero, qrow) + k_cont ----
    k_norm_logits<<<BSZ, 128, 0, s0>>>(logits);
    cudaEventRecord(evA, s0);
    k_cont<<<528, 256, 0, s0>>>();

    // ---- s1: mask bits (DRAM-bound) + exact positives ----
    k_bits<<<2048, 256, 0, s1>>>(pmask);
    cudaStreamWaitEvent(s1, evA, 0);
    k_posbits<<<512, 256, 0, s1>>>();
    cudaEventRecord(ev1, s1);

    // ---- s2: distill chain (tnorm includes Gram zeroing) ----
    k_tnorm<<<512, 256, 0, s2>>>(teach);
    k_transpose_both<<<dim3(28, BSZ / 32), dim3(32, 8), 0, s2>>>(hash, teach);
    k_gemm_all<<<224, 256, 0, s2>>>();
    k_sq3<<<512, 256, 0, s2>>>();
    cudaEventRecord(ev2, s2);

    // ---- join ----
    cudaStreamWaitEvent(s0, ev1, 0);
    cudaStreamWaitEvent(s0, ev2, 0);
    k_combine<<<1, 256, 0, s0>>>(out);
}

// round 17
// speedup vs baseline: 1.2355x; 1.2355x over previous
#include <cuda_runtime.h>
#include <cuda_bf16.h>
#include <math.h>

#define BSZ 4096
#define HD  128
#define TDIM 768

// ---------------- device scratch ----------------
__device__ __align__(16) float g_LN[BSZ * HD];          // normalized logits fp32
__device__ __align__(16) __nv_bfloat16 g_LNh[BSZ * HD]; // normalized logits bf16
__device__ float g_Tn[BSZ];                              // teacher row inv-norms
__device__ __align__(16) __nv_bfloat16 g_Ht16[HD * BSZ];   // hash^T bf16 [128][4096]
__device__ __align__(16) __nv_bfloat16 g_Tt16[TDIM * BSZ]; // norm teacher^T bf16
__device__ float g_GH[HD * HD];
__device__ float g_C [HD * TDIM];
__device__ float g_TT[TDIM * TDIM];
__device__ unsigned g_bm[BSZ * BSZ / 32];  // mask bits [4096][128] u32
__device__ float g_denom[BSZ];
__device__ float g_pos[BSZ];
__device__ float g_cnt[BSZ];
__device__ float g_qrow[BSZ];              // per-row quant sums
__device__ float g_ST;

__device__ __forceinline__ void mma_bf16(float* d, const unsigned* a, const unsigned* b) {
    asm volatile(
        "mma.sync.aligned.m16n8k16.row.col.f32.bf16.bf16.f32 "
        "{%0,%1,%2,%3}, {%4,%5,%6,%7}, {%8,%9}, {%0,%1,%2,%3};"
        : "+f"(d[0]), "+f"(d[1]), "+f"(d[2]), "+f"(d[3])
        : "r"(a[0]), "r"(a[1]), "r"(a[2]), "r"(a[3]), "r"(b[0]), "r"(b[1]));
}

#define LDSM4(r0, r1, r2, r3, addr)                                         \
    asm volatile("ldmatrix.sync.aligned.m8n8.x4.shared.b16 {%0,%1,%2,%3}, [%4];" \
        : "=r"(r0), "=r"(r1), "=r"(r2), "=r"(r3) : "r"(addr))

// ---------------- mask -> bitmask (nibble pack, LDG.128) ----------------
__global__ void k_bits(const int* __restrict__ pmask) {
    int gw = (blockIdx.x * blockDim.x + threadIdx.x) >> 5;   // 16384 warps
    int lane = threadIdx.x & 31;
    const int4* m4 = (const int4*)pmask;
    long base4 = (long)gw * 256;            // 1024 ints = 256 int4 per warp
    #pragma unroll
    for (int rnd = 0; rnd < 8; rnd++) {
        int4 v = m4[base4 + rnd * 32 + lane];
        unsigned nib = (v.x ? 1u : 0u) | (v.y ? 2u : 0u)
                     | (v.z ? 4u : 0u) | (v.w ? 8u : 0u);
        unsigned r = nib << ((lane & 7) * 4);
        r |= __shfl_xor_sync(0xffffffffu, r, 1);
        r |= __shfl_xor_sync(0xffffffffu, r, 2);
        r |= __shfl_xor_sync(0xffffffffu, r, 4);
        if ((lane & 7) == 0)
            g_bm[gw * 32 + rnd * 4 + (lane >> 3)] = r;
    }
}

// ---------------- normalize logits: warp-per-row, shuffle-only --------------
__global__ void k_norm_logits(const float* __restrict__ x) {
    int row = (blockIdx.x * blockDim.x + threadIdx.x) >> 5;  // 4096 warps
    int lane = threadIdx.x & 31;
    const float4* x4 = (const float4*)(x + row * HD);        // 32 float4
    float4 v = x4[lane];
    float ss = v.x * v.x + v.y * v.y + v.z * v.z + v.w * v.w;
    float q = fabsf(fabsf(v.x) - 1.0f) + fabsf(fabsf(v.y) - 1.0f)
            + fabsf(fabsf(v.z) - 1.0f) + fabsf(fabsf(v.w) - 1.0f);
    #pragma unroll
    for (int o = 16; o >= 1; o >>= 1) {
        ss += __shfl_xor_sync(0xffffffffu, ss, o);
        q  += __shfl_xor_sync(0xffffffffu, q, o);
    }
    float sinv = 1.0f / fmaxf(sqrtf(ss), 1e-12f);
    if (lane == 0) { g_qrow[row] = q; g_denom[row] = 0.f; }
    float4 nv = make_float4(v.x * sinv, v.y * sinv, v.z * sinv, v.w * sinv);
    ((float4*)(g_LN + row * HD))[lane] = nv;
    __nv_bfloat162 h0 = {__float2bfloat16(nv.x), __float2bfloat16(nv.y)};
    __nv_bfloat162 h1 = {__float2bfloat16(nv.z), __float2bfloat16(nv.w)};
    ((__nv_bfloat162*)(g_LNh + row * HD))[lane * 2]     = h0;
    ((__nv_bfloat162*)(g_LNh + row * HD))[lane * 2 + 1] = h1;
}

// ---------------- positives: warp-per-row bitmask scan, exact fp32 ----------
__global__ void k_posbits() {
    int warp = (blockIdx.x * blockDim.x + threadIdx.x) >> 5;   // 4096 warps
    int lane = threadIdx.x & 31;
    int row = warp;
    const float4* LN4 = (const float4*)g_LN;   // row stride 32 float4
    float4 a = LN4[row * 32 + lane];
    float ps = 0.f;
    int cnt = 0;
    #pragma unroll
    for (int g = 0; g < 4; g++) {
        unsigned wrd = g_bm[row * 128 + g * 32 + lane];
        unsigned act = __ballot_sync(0xffffffffu, wrd != 0);
        while (act) {
            int src = __ffs(act) - 1; act &= act - 1;
            unsigned w2 = __shfl_sync(0xffffffffu, wrd, src);
            int base = (g * 32 + src) * 32;
            while (w2) {
                int b = __ffs(w2) - 1; w2 &= w2 - 1;
                int j = base + b;
                float4 bb = LN4[j * 32 + lane];
                float d = a.x * bb.x + a.y * bb.y + a.z * bb.z + a.w * bb.w;
                #pragma unroll
                for (int o = 16; o >= 1; o >>= 1)
                    d += __shfl_xor_sync(0xffffffffu, d, o);
                ps += d; cnt++;
            }
        }
    }
    if (lane == 0) { g_pos[row] = ps * 5.0f; g_cnt[row] = (float)cnt; }
}

// ---------------- teacher row inv norms + Gram-accumulator zeroing ----------
__global__ void k_tnorm(const float* __restrict__ x) {
    int gi = blockIdx.x * 256 + threadIdx.x;
    int n = gridDim.x * 256;
    for (int j = gi; j < TDIM * TDIM; j += n) g_TT[j] = 0.f;
    for (int j = gi; j < HD * TDIM;  j += n) g_C[j]  = 0.f;
    if (gi < HD * HD) g_GH[gi] = 0.f;
    if (gi == 0) g_ST = 0.f;
    int row = gi >> 5;                   // 4096 warps
    int lane = threadIdx.x & 31;
    const float4* x4 = (const float4*)(x + row * TDIM);  // 192 float4
    float ss = 0.f;
    #pragma unroll
    for (int i = 0; i < 6; i++) {
        float4 v = x4[lane + i * 32];
        ss += v.x * v.x + v.y * v.y + v.z * v.z + v.w * v.w;
    }
    #pragma unroll
    for (int o = 16; o >= 1; o >>= 1) ss += __shfl_xor_sync(0xffffffffu, ss, o);
    if (lane == 0) g_Tn[row] = 1.0f / fmaxf(sqrtf(ss), 1e-12f);
}

// ---------------- fused transposes -> bf16 (hash + scaled teacher) ----------
__global__ void k_transpose_both(const float* __restrict__ hash,
                                 const float* __restrict__ teach) {
    __shared__ float t[32][33];
    int x = threadIdx.x, y = threadIdx.y;   // block (32, 8)
    int r0 = blockIdx.y * 32;
    if (blockIdx.x < 4) {
        int c0 = blockIdx.x * 32;
        #pragma unroll
        for (int i = 0; i < 32; i += 8) t[y + i][x] = hash[(r0 + y + i) * HD + c0 + x];
        __syncthreads();
        #pragma unroll
        for (int i = 0; i < 32; i += 8)
            g_Ht16[(c0 + y + i) * BSZ + r0 + x] = __float2bfloat16(t[x][y + i]);
    } else {
        int c0 = (blockIdx.x - 4) * 32;
        #pragma unroll
        for (int i = 0; i < 32; i += 8)
            t[y + i][x] = teach[(r0 + y + i) * TDIM + c0 + x] * g_Tn[r0 + y + i];
        __syncthreads();
        #pragma unroll
        for (int i = 0; i < 32; i += 8)
            g_Tt16[(c0 + y + i) * BSZ + r0 + x] = __float2bfloat16(t[x][y + i]);
    }
}

// ======== legacy 128x128 bf16 mma core (Gram GEMMs), LDSM, double-buffer ====
#define LDG16(Aexpr, Bexpr)                                                 \
    do {                                                                    \
        _Pragma("unroll")                                                   \
        for (int s = 0; s < 2; s++) {                                       \
            int idx = tid + s * 256;                                        \
            int r = idx >> 2, c4 = idx & 3;                                 \
            ga[s] = (Aexpr); gb[s] = (Bexpr);                               \
        }                                                                   \
    } while (0)

#define STS16(st)                                                           \
    do {                                                                    \
        _Pragma("unroll")                                                   \
        for (int s = 0; s < 2; s++) {                                       \
            int idx = tid + s * 256;                                        \
            int r = idx >> 2, c4 = idx & 3;                                 \
            *(uint4*)&As16[st][r][c4 * 4] = ga[s];                          \
            *(uint4*)&Bs16[st][r][c4 * 4] = gb[s];                          \
        }                                                                   \
    } while (0)

#define LDSM_BASES()                                                        \
    unsigned aBase = (unsigned)__cvta_generic_to_shared(&As16[0][0][0])     \
        + (((wm * 64 + (lane & 7) + ((lane >> 3) & 1) * 8) * 20             \
            + (lane >> 4) * 4) << 2);                                       \
    unsigned bBase = (unsigned)__cvta_generic_to_shared(&Bs16[0][0][0])     \
        + (((wn * 32 + (lane & 7) + (lane >> 4) * 8) * 20                   \
            + ((lane >> 3) & 1) * 4) << 2)

#define MMA16_CHUNK(st)                                                     \
    do {                                                                    \
        _Pragma("unroll")                                                   \
        for (int kk = 0; kk < 2; kk++) {                                    \
            int kb = kk * 8;                                                \
            unsigned af[4][4], bf[4][2];                                    \
            _Pragma("unroll")                                               \
            for (int mi = 0; mi < 4; mi++)                                  \
                LDSM4(af[mi][0], af[mi][1], af[mi][2], af[mi][3],           \
                      aBase + (st) * 10240 + ((mi * 16 * 20 + kb) << 2));   \
            _Pragma("unroll")                                               \
            for (int n2 = 0; n2 < 2; n2++)                                  \
                LDSM4(bf[2 * n2][0], bf[2 * n2][1],                         \
                      bf[2 * n2 + 1][0], bf[2 * n2 + 1][1],                 \
                      bBase + (st) * 10240 + ((n2 * 16 * 20 + kb) << 2));   \
            _Pragma("unroll")                                               \
            for (int mi = 0; mi < 4; mi++)                                  \
                _Pragma("unroll")                                           \
                for (int ni = 0; ni < 4; ni++)                              \
                    mma_bf16(acc[mi][ni], af[mi], bf[ni]);                  \
        }                                                                   \
    } while (0)

// ---------------- ALL Gram GEMMs in one launch (task-decoded) --------------
__global__ void __launch_bounds__(256) k_gemm_all() {
    __shared__ __align__(16) unsigned As16[2][128][20];
    __shared__ __align__(16) unsigned Bs16[2][128][20];
    int id = blockIdx.x;
    const __nv_bfloat16 *Ap, *Bp;
    float* out;
    int ldo, m0, n0, kBeg, nCh;
    if (id < 336) {
        int tile = id / 16, split = id % 16;
        int tm = 0, t = tile;
        while (t >= 6 - tm) { t -= 6 - tm; tm++; }
        m0 = tm * 128; n0 = (tm + t) * 128;
        kBeg = split * 256; nCh = 8;
        Ap = g_Tt16; Bp = g_Tt16; out = g_TT; ldo = TDIM;
    } else if (id < 432) {
        int t = id - 336;
        int tile = t / 16, split = t % 16;
        m0 = 0; n0 = tile * 128;
        kBeg = split * 256; nCh = 8;
        Ap = g_Ht16; Bp = g_Tt16; out = g_C; ldo = TDIM;
    } else {
        int split = id - 432;
        m0 = 0; n0 = 0;
        kBeg = split * 128; nCh = 4;
        Ap = g_Ht16; Bp = g_Ht16; out = g_GH; ldo = HD;
    }
    int tid = threadIdx.x, lane = tid & 31, w = tid >> 5;
    int wm = w & 1, wn = w >> 1;
    int fr = lane >> 2, fc = lane & 3;
    LDSM_BASES();
    const uint4* A4 = (const uint4*)Ap;    // row = 512 uint4
    const uint4* B4 = (const uint4*)Bp;
    float acc[4][4][4] = {};
    uint4 ga[2], gb[2];
    LDG16(A4[(m0 + r) * 512 + (kBeg >> 3) + c4],
          B4[(n0 + r) * 512 + (kBeg >> 3) + c4]);
    STS16(0);
    __syncthreads();
    for (int c = 0; c < nCh; c++) {
        int st = c & 1;
        if (c + 1 < nCh) {
            int kc = kBeg + (c + 1) * 32;
            LDG16(A4[(m0 + r) * 512 + (kc >> 3) + c4],
                  B4[(n0 + r) * 512 + (kc >> 3) + c4]);
        }
        MMA16_CHUNK(st);
        if (c + 1 < nCh) STS16(1 - st);
        __syncthreads();
    }
    #pragma unroll
    for (int mi = 0; mi < 4; mi++)
        #pragma unroll
        for (int ni = 0; ni < 4; ni++)
            #pragma unroll
            for (int h = 0; h < 2; h++)
                #pragma unroll
                for (int q = 0; q < 2; q++) {
                    int gi = m0 + wm * 64 + mi * 16 + fr + h * 8;
                    int gj = n0 + wn * 32 + ni * 8 + fc * 2 + q;
                    atomicAdd(&out[gi * ldo + gj], acc[mi][ni][h * 2 + q]);
                }
}

// ---------------- distill square-reduce ----------------
__global__ void k_sq3() {
    int i = blockIdx.x * 256 + threadIdx.x;
    int n = gridDim.x * 256;
    float s = 0.f;
    for (int j = i; j < HD * HD; j += n) {
        float v = g_GH[j]; s += v * v * (1.f / (128.f * 128.f));
    }
    for (int j = i; j < HD * TDIM; j += n) {
        float v = g_C[j]; s -= 2.f * v * v * (1.f / 128.f);
    }
    for (int j = i; j < TDIM * TDIM; j += n) {
        int r = j / TDIM, c = j % TDIM;
        if (c < r) continue;
        float v = g_TT[j];
        s += (c == r) ? v * v : 2.f * v * v;
    }
    #pragma unroll
    for (int o = 16; o >= 1; o >>= 1) s += __shfl_xor_sync(0xffffffffu, s, o);
    __shared__ float red[8];
    if ((threadIdx.x & 31) == 0) red[threadIdx.x >> 5] = s;
    __syncthreads();
    if (threadIdx.x == 0) {
        float tot = 0.f;
        #pragma unroll
        for (int k = 0; k < 8; k++) tot += red[k];
        atomicAdd(&g_ST, tot / ((float)BSZ * (float)BSZ));
    }
}

// ---------------- contrastive: persistent, full-K single-buffer tiles -------
// dyn smem: As [128][68] u32, Bs [128][68] u32 -> 69632 bytes, one sync/tile.
#define CONT_SMEM (2 * 128 * 68 * 4)
#define CONT_GRID 444
__global__ void __launch_bounds__(256) k_cont() {
    extern __shared__ unsigned dyn[];
    unsigned (*As16)[68] = (unsigned (*)[68])dyn;
    unsigned (*Bs16)[68] = (unsigned (*)[68])(dyn + 128 * 68);
    __shared__ float sCd[128];
    int tid = threadIdx.x, lane = tid & 31, w = tid >> 5;
    int wm = w & 1, wn = w >> 1;
    int fr = lane >> 2, fc = lane & 3;
    unsigned aBase = (unsigned)__cvta_generic_to_shared(&As16[0][0])
        + (((wm * 64 + (lane & 7) + ((lane >> 3) & 1) * 8) * 68
            + (lane >> 4) * 4) << 2);
    unsigned bBase = (unsigned)__cvta_generic_to_shared(&Bs16[0][0])
        + (((wn * 32 + (lane & 7) + (lane >> 4) * 8) * 68
            + ((lane >> 3) & 1) * 4) << 2);
    const uint4* LN4 = (const uint4*)g_LNh;   // row = 16 uint4 (128 bf16)

    for (int tt = blockIdx.x; tt < 528; tt += CONT_GRID) {
        int t = tt, tm = 0;
        while (t >= 32 - tm) { t -= 32 - tm; tm++; }
        int i0 = tm * 128, j0 = (tm + t) * 128;
        bool diag = (i0 == j0);
        if (tid < 128) sCd[tid] = 0.f;
        #pragma unroll
        for (int s = 0; s < 8; s++) {
            int idx = tid + s * 256;
            int r = idx >> 4, c4 = idx & 15;
            *(uint4*)&As16[r][c4 * 4] = LN4[(i0 + r) * 16 + c4];
            *(uint4*)&Bs16[r][c4 * 4] = LN4[(j0 + r) * 16 + c4];
        }
        __syncthreads();
        float acc[4][4][4] = {};
        #pragma unroll
        for (int kk = 0; kk < 8; kk++) {
            int kb = kk * 8;
            unsigned af[4][4], bf[4][2];
            #pragma unroll
            for (int mi = 0; mi < 4; mi++)
                LDSM4(af[mi][0], af[mi][1], af[mi][2], af[mi][3],
                      aBase + ((mi * 16 * 68 + kb) << 2));
            #pragma unroll
            for (int n2 = 0; n2 < 2; n2++)
                LDSM4(bf[2 * n2][0], bf[2 * n2][1],
                      bf[2 * n2 + 1][0], bf[2 * n2 + 1][1],
                      bBase + ((n2 * 16 * 68 + kb) << 2));
            #pragma unroll
            for (int mi = 0; mi < 4; mi++)
                #pragma unroll
                for (int ni = 0; ni < 4; ni++)
                    mma_bf16(acc[mi][ni], af[mi], bf[ni]);
        }

        // ---- epilogue: exp sums, both orientations ----
        float dR[4][2] = {}, dC[4][2] = {};
        #pragma unroll
        for (int mi = 0; mi < 4; mi++)
            #pragma unroll
            for (int ni = 0; ni < 4; ni++)
                #pragma unroll
                for (int h = 0; h < 2; h++)
                    #pragma unroll
                    for (int q = 0; q < 2; q++) {
                        int li = wm * 64 + mi * 16 + fr + h * 8;
                        int lj = wn * 32 + ni * 8 + fc * 2 + q;
                        float e = __expf(acc[mi][ni][h * 2 + q] * 5.0f);
                        if (!diag || li != lj) dR[mi][h] += e;
                        if (!diag) dC[ni][q] += e;
                    }
        #pragma unroll
        for (int mi = 0; mi < 4; mi++)
            #pragma unroll
            for (int h = 0; h < 2; h++) {
                #pragma unroll
                for (int o = 2; o >= 1; o >>= 1)
                    dR[mi][h] += __shfl_down_sync(0xffffffffu, dR[mi][h], o, 4);
                if (fc == 0)
                    atomicAdd(&g_denom[i0 + wm * 64 + mi * 16 + fr + h * 8],
                              dR[mi][h]);
            }
        if (!diag) {
            #pragma unroll
            for (int ni = 0; ni < 4; ni++)
                #pragma unroll
                for (int q = 0; q < 2; q++) {
                    #pragma unroll
                    for (int o = 16; o >= 4; o >>= 1)
                        dC[ni][q] += __shfl_xor_sync(0xffffffffu, dC[ni][q], o);
                    if (fr == 0)
                        atomicAdd(&sCd[wn * 32 + ni * 8 + fc * 2 + q], dC[ni][q]);
                }
            __syncthreads();
            if (tid < 128) atomicAdd(&g_denom[j0 + tid], sCd[tid]);
        }
        __syncthreads();
    }
}

// ---------------- final combine ----------------
__global__ void k_combine(float* __restrict__ out) {
    int tid = threadIdx.x;               // 256 threads
    float cont = 0.f, qs = 0.f;
    for (int i = tid; i < BSZ; i += 256) {
        cont += logf(g_denom[i]) - g_pos[i] / fmaxf(g_cnt[i], 1.0f);
        qs   += g_qrow[i];
    }
    #pragma unroll
    for (int o = 16; o >= 1; o >>= 1) {
        cont += __shfl_xor_sync(0xffffffffu, cont, o);
        qs   += __shfl_xor_sync(0xffffffffu, qs, o);
    }
    __shared__ float r0[8], r1[8];
    if ((tid & 31) == 0) { r0[tid >> 5] = cont; r1[tid >> 5] = qs; }
    __syncthreads();
    if (tid == 0) {
        float cT = 0.f, qT = 0.f;
        #pragma unroll
        for (int i = 0; i < 8; i++) { cT += r0[i]; qT += r1[i]; }
        float quant = qT / ((float)BSZ * (float)HD);
        out[0] = cT / (float)BSZ + 0.5f * g_ST + 0.01f * quant;
    }
}

// ---------------- launch: fork-join across 3 streams ----------------
extern "C" void kernel_launch(void* const* d_in, const int* in_sizes, int n_in,
                              void* d_out, int out_size) {
    const float* logits = (const float*)d_in[0];
    const float* hash   = (const float*)d_in[1];
    const float* teach  = (const float*)d_in[2];
    const int*   pmask  = (const int*)d_in[3];
    float* out = (float*)d_out;

    static cudaStream_t s1 = 0, s2 = 0;
    static cudaEvent_t evStart = 0, evA = 0, ev1 = 0, ev2 = 0;
    if (s1 == 0) {
        cudaStreamCreateWithFlags(&s1, cudaStreamNonBlocking);
        cudaStreamCreateWithFlags(&s2, cudaStreamNonBlocking);
        cudaEventCreateWithFlags(&evStart, cudaEventDisableTiming);
        cudaEventCreateWithFlags(&evA, cudaEventDisableTiming);
        cudaEventCreateWithFlags(&ev1, cudaEventDisableTiming);
        cudaEventCreateWithFlags(&ev2, cudaEventDisableTiming);
        cudaFuncSetAttribute(k_cont, cudaFuncAttributeMaxDynamicSharedMemorySize,
                             CONT_SMEM);
    }
    cudaStream_t s0 = 0;   // legacy default (capture) stream

    cudaEventRecord(evStart, s0);
    cudaStreamWaitEvent(s1, evStart, 0);
    cudaStreamWaitEvent(s2, evStart, 0);

    // ---- main: logits chain (+denom zero, qrow) + k_cont ----
    k_norm_logits<<<512, 256, 0, s0>>>(logits);
    cudaEventRecord(evA, s0);
    k_cont<<<CONT_GRID, 256, CONT_SMEM, s0>>>();

    // ---- s1: mask bits (DRAM-bound) + exact positives ----
    k_bits<<<2048, 256, 0, s1>>>(pmask);
    cudaStreamWaitEvent(s1, evA, 0);
    k_posbits<<<512, 256, 0, s1>>>();
    cudaEventRecord(ev1, s1);

    // ---- s2: distill chain (tnorm includes Gram zeroing) ----
    k_tnorm<<<512, 256, 0, s2>>>(teach);
    k_transpose_both<<<dim3(28, BSZ / 32), dim3(32, 8), 0, s2>>>(hash, teach);
    k_gemm_all<<<464, 256, 0, s2>>>();
    k_sq3<<<512, 256, 0, s2>>>();
    cudaEventRecord(ev2, s2);

    // ---- join ----
    cudaStreamWaitEvent(s0, ev1, 0);
    cudaStreamWaitEvent(s0, ev2, 0);
    k_combine<<<1, 256, 0, s0>>>(out);
}